// round 13
// baseline (speedup 1.0000x reference)
#include <cuda_runtime.h>
#include <cuda_fp16.h>
#include <cstdint>
#include <math.h>

// ---------------------------------------------------------------------------
// Problem constants
// ---------------------------------------------------------------------------
#define NPTS      98304
#define NPB       49152
#define DH        512
#define NBLK      5
#define NFREQ     10
#define IMGH      128
#define IMGW      128
#define DENC      64
#define NPIX      (IMGH * IMGW)
#define DCAT      1024                  // [al | u] concat K
#define DIN       (DENC + DH)           // [ench | al] concat K = 576
#define ACAT      (DENC + DH + DH)      // activation row stride = 1088
#define OFF_AL    DENC                  // 64
#define OFF_U     (DENC + DH)           // 576

// ---------------------------------------------------------------------------
// Scratch
// ---------------------------------------------------------------------------
__device__ float  g_uv[NPTS * 2];
__device__ float  g_h[NPTS * DH];              // fp32 residual stream
__device__ __half g_featT[2 * NPIX * DH];      // transposed features [b][pix][c]
__device__ __half g_acat[NPTS * ACAT];         // [ench | al | u]
__device__ __half g_t[NPTS * DH];              // relu(h)
__device__ __half g_wcat0[DH * DIN];           // [n][ Win | Wz0 ]
__device__ __half g_w0[NBLK * DH * DH];        // fc0 [l][n][k]
__device__ __half g_wcat[(NBLK - 1) * DH * DCAT]; // [i][n][ Wz_{i+1} | W1_i ]
__device__ __half g_w1l[DH * DH];              // W1 layer4 [n][k]
__device__ float  g_b0[DH];                    // lin_in_b + lin_z_b[0]
__device__ float  g_bcat[(NBLK - 1) * DH];     // b1_i + bz_{i+1}

// ---------------------------------------------------------------------------
// PTX helpers
// ---------------------------------------------------------------------------
__device__ __forceinline__ uint32_t smem_u32(const void* p) {
    uint32_t a;
    asm("{ .reg .u64 t; cvta.to.shared.u64 t, %1; cvt.u32.u64 %0, t; }" : "=r"(a) : "l"(p));
    return a;
}
__device__ __forceinline__ void ldsm_x4(uint32_t& r0, uint32_t& r1, uint32_t& r2,
                                        uint32_t& r3, uint32_t addr) {
    asm volatile("ldmatrix.sync.aligned.m8n8.x4.shared.b16 {%0,%1,%2,%3}, [%4];"
                 : "=r"(r0), "=r"(r1), "=r"(r2), "=r"(r3) : "r"(addr));
}
__device__ __forceinline__ void mma_f16(float* d, const uint32_t* a, const uint32_t* b) {
    asm volatile(
        "mma.sync.aligned.m16n8k16.row.col.f32.f16.f16.f32 "
        "{%0,%1,%2,%3}, {%4,%5,%6,%7}, {%8,%9}, {%0,%1,%2,%3};"
        : "+f"(d[0]), "+f"(d[1]), "+f"(d[2]), "+f"(d[3])
        : "r"(a[0]), "r"(a[1]), "r"(a[2]), "r"(a[3]), "r"(b[0]), "r"(b[1]));
}
__device__ __forceinline__ void cp16(uint32_t dst, const void* src) {
    asm volatile("cp.async.cg.shared.global [%0], [%1], 16;" :: "r"(dst), "l"(src));
}
#define CP_COMMIT() asm volatile("cp.async.commit_group;" ::: "memory")
#define CP_WAIT(n)  asm volatile("cp.async.wait_group %0;" :: "n"(n) : "memory")

// ---------------------------------------------------------------------------
// Prep kernels
// ---------------------------------------------------------------------------
__global__ void enc_kernel(const float* __restrict__ xyz,
                           const float* __restrict__ c2w,
                           const float* __restrict__ kmat) {
    int n = blockIdx.x * blockDim.x + threadIdx.x;
    if (n >= NPTS) return;
    int b = n / NPB;
    float p0 = xyz[n * 3 + 0], p1 = xyz[n * 3 + 1], p2 = xyz[n * 3 + 2];
    const float* M = c2w + b * 16;
    float q0 = p0 - M[3], q1 = p1 - M[7], q2 = p2 - M[11];
    float cam[3];
    #pragma unroll
    for (int i = 0; i < 3; i++)
        cam[i] = M[0 * 4 + i] * q0 + M[1 * 4 + i] * q1 + M[2 * 4 + i] * q2;
    const float* K = kmat + b * 9;
    float uw = K[0] * cam[0] + K[1] * cam[1] + K[2] * cam[2];
    float vw = K[3] * cam[0] + K[4] * cam[1] + K[5] * cam[2];
    float zw = K[6] * cam[0] + K[7] * cam[1] + K[8] * cam[2];
    float z = (fabsf(zw) < 1e-6f) ? 1e-6f : zw;
    g_uv[n * 2 + 0] = uw / z;
    g_uv[n * 2 + 1] = vw / z;
    __half* E = g_acat + (size_t)n * ACAT;     // ench at offset 0
    E[0] = __float2half_rn(cam[0]);
    E[1] = __float2half_rn(cam[1]);
    E[2] = __float2half_rn(cam[2]);
    const float TWO_PI = 6.283185307179586f;
    #pragma unroll
    for (int axis = 0; axis < 3; axis++)
        #pragma unroll
        for (int f = 0; f < NFREQ; f++) {
            float s = TWO_PI * cam[axis] * (float)(1 << f);
            E[3  + axis * NFREQ + f] = __float2half_rn(sinf(s));
            E[33 + axis * NFREQ + f] = __float2half_rn(cosf(s));
        }
    E[63] = __float2half_rn(0.0f);
}

// features [b][c][y][x] fp32 -> g_featT [b][pix][c] fp16
__global__ void transpose_feat_kernel(const float* __restrict__ feat) {
    __shared__ __half tile[32][33];
    int pxt = blockIdx.x;
    int ct  = blockIdx.y;
    int b   = blockIdx.z;
    int tid = threadIdx.x;
    int col = tid & 31;
    int rowb = tid >> 5;
    const float* fb = feat + (size_t)b * DH * NPIX;
    #pragma unroll
    for (int i = 0; i < 4; i++) {
        int c = ct * 32 + rowb + i * 8;
        tile[rowb + i * 8][col] = __float2half_rn(fb[(size_t)c * NPIX + pxt * 32 + col]);
    }
    __syncthreads();
    __half* ob = g_featT + ((size_t)b * NPIX + pxt * 32) * DH + ct * 32;
    #pragma unroll
    for (int i = 0; i < 4; i++) {
        int px = rowb + i * 8;
        ob[(size_t)px * DH + col] = tile[col][px];
    }
}

// bilinear -> al section of g_acat (stride ACAT, offset OFF_AL)
__global__ void bilinear_kernel() {
    int n = blockIdx.x * 8 + (threadIdx.x >> 5);
    int lane = threadIdx.x & 31;
    if (n >= NPTS) return;
    int b = n / NPB;
    float u = g_uv[n * 2 + 0], v = g_uv[n * 2 + 1];
    float x = fminf(fmaxf(u, 0.0f), (float)(IMGW - 1));
    float y = fminf(fmaxf(v, 0.0f), (float)(IMGH - 1));
    float x0 = floorf(x), y0 = floorf(y);
    int x0i = (int)x0, y0i = (int)y0;
    int x1i = min(x0i + 1, IMGW - 1);
    int y1i = min(y0i + 1, IMGH - 1);
    float wx = x - x0, wy = y - y0;
    float w00 = (1.0f - wx) * (1.0f - wy);
    float w01 = wx * (1.0f - wy);
    float w10 = (1.0f - wx) * wy;
    float w11 = wx * wy;
    const __half* base = g_featT + (size_t)b * NPIX * DH;
    const __half* p00 = base + (size_t)(y0i * IMGW + x0i) * DH;
    const __half* p01 = base + (size_t)(y0i * IMGW + x1i) * DH;
    const __half* p10 = base + (size_t)(y1i * IMGW + x0i) * DH;
    const __half* p11 = base + (size_t)(y1i * IMGW + x1i) * DH;
    __half* out = g_acat + (size_t)n * ACAT + OFF_AL;
    #pragma unroll
    for (int rep = 0; rep < 2; rep++) {
        int c0 = rep * 256 + lane * 8;
        uint4 a = *(const uint4*)(p00 + c0);
        uint4 bq = *(const uint4*)(p01 + c0);
        uint4 cq = *(const uint4*)(p10 + c0);
        uint4 dq = *(const uint4*)(p11 + c0);
        const __half2* ah = (const __half2*)&a;
        const __half2* bh = (const __half2*)&bq;
        const __half2* ch = (const __half2*)&cq;
        const __half2* dh = (const __half2*)&dq;
        uint4 o;
        __half2* oh = (__half2*)&o;
        #pragma unroll
        for (int i = 0; i < 4; i++) {
            float2 fa = __half22float2(ah[i]);
            float2 fbv = __half22float2(bh[i]);
            float2 fc = __half22float2(ch[i]);
            float2 fd = __half22float2(dh[i]);
            float r0 = fa.x * w00 + fbv.x * w01 + fc.x * w10 + fd.x * w11;
            float r1 = fa.y * w00 + fbv.y * w01 + fc.y * w10 + fd.y * w11;
            oh[i] = __floats2half2_rn(r0, r1);
        }
        *(uint4*)(out + c0) = o;
    }
}

// W[l][k][n] fp32 -> O [l][n][k] fp16 (all NBLK layers)
__global__ void conv_w_kernel(const float* __restrict__ W, __half* __restrict__ O,
                              int total) {
    int idx = blockIdx.x * blockDim.x + threadIdx.x;
    if (idx >= total) return;
    int l = idx >> 18;
    int rem = idx & 262143;
    int k = rem >> 9;
    int n = rem & 511;
    O[(l << 18) + n * DH + k] = __float2half_rn(W[idx]);
}

// single layer W[k][n] -> O[n][k]
__global__ void conv_w1_kernel(const float* __restrict__ W, __half* __restrict__ O) {
    int idx = blockIdx.x * blockDim.x + threadIdx.x;
    if (idx >= DH * DH) return;
    int k = idx >> 9, n = idx & 511;
    O[n * DH + k] = __float2half_rn(W[idx]);
}

// g_wcat0[n][k]: k<64 -> lin_in_w[k][n] (pad 63), else Wz0[k-64][n]
__global__ void conv_wcat0_kernel(const float* __restrict__ Win,
                                  const float* __restrict__ Wz) {
    int idx = blockIdx.x * blockDim.x + threadIdx.x;
    if (idx >= DH * DIN) return;
    int n = idx / DIN;
    int k = idx % DIN;
    float v;
    if (k < DENC) v = (k < 63) ? Win[k * DH + n] : 0.0f;
    else          v = Wz[(size_t)(k - DENC) * DH + n];
    g_wcat0[n * DIN + k] = __float2half_rn(v);
}

// concat weights: g_wcat[i][n][k<512: Wz_{i+1}[k][n] ; k>=512: W1_i[k-512][n]]
__global__ void conv_wcat_kernel(const float* __restrict__ Wz,
                                 const float* __restrict__ W1) {
    int idx = blockIdx.x * blockDim.x + threadIdx.x;
    if (idx >= (NBLK - 1) * DH * DCAT) return;
    int i = idx / (DH * DCAT);
    int rem = idx % (DH * DCAT);
    int n = rem >> 10;
    int k = rem & 1023;
    float v;
    if (k < DH) v = Wz[(size_t)(i + 1) * DH * DH + k * DH + n];
    else        v = W1[(size_t)i * DH * DH + (k - DH) * DH + n];
    g_wcat[(size_t)i * DH * DCAT + n * DCAT + k] = __float2half_rn(v);
}

// g_b0 = lin_in_b + lin_z_b[0];  g_bcat[i] = fc1_b[i] + lin_z_b[i+1]
__global__ void bias_kernel(const float* __restrict__ bin,
                            const float* __restrict__ bz,
                            const float* __restrict__ b1) {
    int idx = blockIdx.x * blockDim.x + threadIdx.x;
    if (idx < DH) g_b0[idx] = bin[idx] + bz[idx];
    idx -= DH;
    if (idx >= 0 && idx < (NBLK - 1) * DH) {
        int i = idx >> 9, n = idx & 511;
        g_bcat[idx] = b1[i * DH + n] + bz[(i + 1) * DH + n];
    }
}

// ---------------------------------------------------------------------------
// fp16 GEMM: mma.sync.m16n8k16, 4-stage cp.async, block 128x256, 512 threads,
// 16 warps in 4x4 grid of 32x64 warp tiles (16 warps/SM preserved at 1 CTA/SM;
// grid.x halves -> A gmem traffic halves).
// A: [m][lda] (Klen consumed). B: [n][Klen] packed. h stride DH, fp16 out ldo.
// ---------------------------------------------------------------------------
#define TBM 128
#define TBN 256
#define TBK 32
#define STG_A 0
#define STG_B 8192
#define STAGEB 24576
#define NSTAGE 4
#define SMEMSZ (NSTAGE * STAGEB)   // 96KB

#define SWOFF(r, ch) ((uint32_t)((r) * 64 + 16 * ((ch) ^ (((r) >> 1) & 3))))

template <bool ACCUM, bool WF32, bool WHALF>
__global__ void __launch_bounds__(512, 1)
gemm_tc_kernel(const __half* __restrict__ Aw, const __half* __restrict__ Bw,
               const float* __restrict__ bias, float* __restrict__ Cf,
               __half* __restrict__ Oh, int Klen, int lda, int ldo) {
    extern __shared__ char smem[];
    const uint32_t sbase = smem_u32(smem);
    const int tid = threadIdx.x;
    const int lane = tid & 31;
    const int wid = tid >> 5;
    const int wm = wid & 3;          // 4 warp row groups (32 rows)
    const int wn = wid >> 2;         // 4 warp col groups (64 cols)
    const int m0 = blockIdx.y * TBM;
    const int n0 = blockIdx.x * TBN;
    const int NCH = Klen >> 5;

    const __half* pA = Aw + (size_t)m0 * lda;
    const __half* pB = Bw + (size_t)n0 * Klen;

    float acc[2][8][4];
    #pragma unroll
    for (int t = 0; t < 2; t++)
        #pragma unroll
        for (int j = 0; j < 8; j++)
            #pragma unroll
            for (int q = 0; q < 4; q++) acc[t][j][q] = 0.0f;

    // loader: A 512 + B 1024 lines of 16B, 3 per thread (512 threads)
    auto load_stage = [&](int c) {
        const uint32_t bb = sbase + (c & (NSTAGE - 1)) * STAGEB;
        const int k0 = c * TBK;
        {   // A: 512 lines
            int r = tid >> 2, ch = tid & 3;
            cp16(bb + STG_A + SWOFF(r, ch), pA + (size_t)r * lda + k0 + ch * 8);
        }
        #pragma unroll
        for (int i = 0; i < 2; i++) {   // B: 1024 lines
            int idx = tid + i * 512;
            int r = idx >> 2, ch = idx & 3;
            cp16(bb + STG_B + SWOFF(r, ch), pB + (size_t)r * Klen + k0 + ch * 8);
        }
    };

    #pragma unroll
    for (int p = 0; p < NSTAGE - 1; p++) {
        if (p < NCH) load_stage(p);
        CP_COMMIT();
    }

    for (int c = 0; c < NCH; c++) {
        CP_WAIT(NSTAGE - 2);
        __syncthreads();
        if (c + NSTAGE - 1 < NCH) load_stage(c + NSTAGE - 1);
        CP_COMMIT();

        const uint32_t bb = sbase + (c & (NSTAGE - 1)) * STAGEB;
        #pragma unroll
        for (int s = 0; s < 2; s++) {
            uint32_t ah[2][4], bh[8][2];
            #pragma unroll
            for (int t = 0; t < 2; t++) {
                int r = wm * 32 + t * 16 + (lane & 15);
                int ch = 2 * s + (lane >> 4);
                ldsm_x4(ah[t][0], ah[t][1], ah[t][2], ah[t][3], bb + STG_A + SWOFF(r, ch));
            }
            #pragma unroll
            for (int p = 0; p < 4; p++) {
                int nr = wn * 64 + p * 16 + (lane & 7) + ((lane >> 4) << 3);
                int ch = 2 * s + ((lane >> 3) & 1);
                ldsm_x4(bh[2 * p][0], bh[2 * p][1], bh[2 * p + 1][0], bh[2 * p + 1][1],
                        bb + STG_B + SWOFF(nr, ch));
            }
            #pragma unroll
            for (int t = 0; t < 2; t++)
                #pragma unroll
                for (int j = 0; j < 8; j++)
                    mma_f16(acc[t][j], ah[t], bh[j]);
        }
    }

    // ---- epilogue ----
    #pragma unroll
    for (int t = 0; t < 2; t++) {
        #pragma unroll
        for (int half = 0; half < 2; half++) {
            int m = m0 + wm * 32 + t * 16 + half * 8 + (lane >> 2);
            float* crow = (WF32 || ACCUM) ? (Cf + (size_t)m * DH) : nullptr;
            #pragma unroll
            for (int j = 0; j < 8; j++) {
                int col = n0 + wn * 64 + j * 8 + (lane & 3) * 2;
                float v0 = acc[t][j][half * 2 + 0] + bias[col];
                float v1 = acc[t][j][half * 2 + 1] + bias[col + 1];
                if (ACCUM) {
                    float2 o = *(const float2*)(crow + col);
                    v0 += o.x; v1 += o.y;
                }
                if (WF32) *(float2*)(crow + col) = make_float2(v0, v1);
                if (WHALF) {
                    __half h0 = __float2half_rn(fmaxf(v0, 0.0f));
                    __half h1 = __float2half_rn(fmaxf(v1, 0.0f));
                    *(__half2*)(Oh + (size_t)m * ldo + col) = __half2{h0, h1};
                }
            }
        }
    }
}

// ---------------------------------------------------------------------------
// sigma = exp(relu(h) @ w_out + b_out), one warp per point
// ---------------------------------------------------------------------------
__global__ void sigma_kernel(const float* __restrict__ w_out,
                             const float* __restrict__ b_out,
                             float* __restrict__ out) {
    int gtid = blockIdx.x * blockDim.x + threadIdx.x;
    int n = gtid >> 5, lane = gtid & 31;
    if (n >= NPTS) return;
    const float* hrow = g_h + (size_t)n * DH;
    float s = 0.0f;
    #pragma unroll
    for (int k = lane; k < DH; k += 32)
        s = fmaf(fmaxf(hrow[k], 0.0f), w_out[k], s);
    #pragma unroll
    for (int off = 16; off > 0; off >>= 1)
        s += __shfl_down_sync(0xFFFFFFFF, s, off);
    if (lane == 0) out[n] = expf(s + b_out[0]);
}

// ---------------------------------------------------------------------------
// Launch
// ---------------------------------------------------------------------------
template <typename T>
static T* sym(const T& s) {
    void* p = nullptr;
    cudaGetSymbolAddress(&p, s);
    return (T*)p;
}

extern "C" void kernel_launch(void* const* d_in, const int* in_sizes, int n_in,
                              void* d_out, int out_size) {
    const float* world_xyz = (const float*)d_in[0];
    const float* c2w       = (const float*)d_in[1];
    const float* k_mat     = (const float*)d_in[2];
    const float* features  = (const float*)d_in[3];
    const float* lin_in_w  = (const float*)d_in[4];
    const float* lin_in_b  = (const float*)d_in[5];
    const float* lin_z_w   = (const float*)d_in[6];
    const float* lin_z_b   = (const float*)d_in[7];
    const float* fc0_w     = (const float*)d_in[8];
    const float* fc0_b     = (const float*)d_in[9];
    const float* fc1_w     = (const float*)d_in[10];
    const float* fc1_b     = (const float*)d_in[11];
    const float* lin_out_w = (const float*)d_in[12];
    const float* lin_out_b = (const float*)d_in[13];
    float* out = (float*)d_out;

    cudaFuncSetAttribute(gemm_tc_kernel<false, true,  true >, cudaFuncAttributeMaxDynamicSharedMemorySize, SMEMSZ);
    cudaFuncSetAttribute(gemm_tc_kernel<true,  true,  true >, cudaFuncAttributeMaxDynamicSharedMemorySize, SMEMSZ);
    cudaFuncSetAttribute(gemm_tc_kernel<false, false, true >, cudaFuncAttributeMaxDynamicSharedMemorySize, SMEMSZ);
    cudaFuncSetAttribute(gemm_tc_kernel<true,  true,  false>, cudaFuncAttributeMaxDynamicSharedMemorySize, SMEMSZ);

    float*  p_h     = (float*)sym(g_h);
    __half* p_acat  = (__half*)sym(g_acat);
    __half* p_t     = (__half*)sym(g_t);
    __half* p_wcat0 = (__half*)sym(g_wcat0);
    __half* p_w0    = (__half*)sym(g_w0);
    __half* p_wcat  = (__half*)sym(g_wcat);
    __half* p_w1l   = (__half*)sym(g_w1l);
    float*  p_b0    = (float*)sym(g_b0);
    float*  p_bcat  = (float*)sym(g_bcat);

    enc_kernel<<<(NPTS + 255) / 256, 256>>>(world_xyz, c2w, k_mat);
    transpose_feat_kernel<<<dim3(NPIX / 32, DH / 32, 2), 256>>>(features);
    bilinear_kernel<<<NPTS / 8, 256>>>();

    conv_w_kernel<<<(NBLK * DH * DH + 255) / 256, 256>>>(fc0_w, p_w0, NBLK * DH * DH);
    conv_w1_kernel<<<(DH * DH + 255) / 256, 256>>>(fc1_w + (size_t)(NBLK - 1) * DH * DH, p_w1l);
    conv_wcat0_kernel<<<(DH * DIN + 255) / 256, 256>>>(lin_in_w, lin_z_w);
    conv_wcat_kernel<<<((NBLK - 1) * DH * DCAT + 255) / 256, 256>>>(lin_z_w, fc1_w);
    bias_kernel<<<(NBLK * DH + 255) / 256, 256>>>(lin_in_b, lin_z_b, fc1_b);

    dim3 grid(DH / TBN, NPTS / TBM);   // (2, 768)

    // h = [ench|al] @ [Win|Wz0] + (b_in + bz0) ; t = relu(h)
    gemm_tc_kernel<false, true, true><<<grid, 512, SMEMSZ>>>(
        p_acat, p_wcat0, p_b0, p_h, p_t, DIN, ACAT, DH);

    for (int i = 0; i < NBLK; i++) {
        // u = relu(t @ W0_i + b0_i)  -> g_acat u section
        gemm_tc_kernel<false, false, true><<<grid, 512, SMEMSZ>>>(
            p_t, p_w0 + (size_t)i * DH * DH, fc0_b + (size_t)i * DH,
            nullptr, p_acat + OFF_U, DH, DH, ACAT);
        if (i < NBLK - 1) {
            // h += [al|u] @ [Wz_{i+1}|W1_i] + (b1_i + bz_{i+1}) ; t = relu(h)
            gemm_tc_kernel<true, true, true><<<grid, 512, SMEMSZ>>>(
                p_acat + OFF_AL, p_wcat + (size_t)i * DH * DCAT, p_bcat + (size_t)i * DH,
                p_h, p_t, DCAT, ACAT, DH);
        } else {
            // h += u @ W1_4 + b1_4
            gemm_tc_kernel<true, true, false><<<grid, 512, SMEMSZ>>>(
                p_acat + OFF_U, p_w1l, fc1_b + (size_t)(NBLK - 1) * DH,
                p_h, nullptr, DH, ACAT, 0);
        }
    }

    sigma_kernel<<<(NPTS * 32 + 255) / 256, 256>>>(lin_out_w, lin_out_b, out);
}

// round 14
// speedup vs baseline: 1.2946x; 1.2946x over previous
#include <cuda_runtime.h>
#include <cuda_fp16.h>
#include <cstdint>
#include <math.h>

// ---------------------------------------------------------------------------
// Problem constants
// ---------------------------------------------------------------------------
#define NPTS      98304
#define NPB       49152
#define DH        512
#define NBLK      5
#define NFREQ     10
#define IMGH      128
#define IMGW      128
#define DENC      64
#define NPIX      (IMGH * IMGW)
#define DCAT      1024                  // [al | u] concat K
#define DIN       (DENC + DH)           // [ench | al] concat K = 576
#define ACAT      (DENC + DH + DH)      // activation row stride = 1088
#define OFF_AL    DENC                  // 64
#define OFF_U     (DENC + DH)           // 576

// ---------------------------------------------------------------------------
// Scratch
// ---------------------------------------------------------------------------
__device__ float  g_uv[NPTS * 2];
__device__ float  g_h[NPTS * DH];              // fp32 residual stream
__device__ __half g_featT[2 * NPIX * DH];      // transposed features [b][pix][c]
__device__ __half g_acat[NPTS * ACAT];         // [ench | al | u]
__device__ __half g_t[NPTS * DH];              // relu(h)
__device__ __half g_wcat0[DH * DIN];           // [n][ Win | Wz0 ]
__device__ __half g_w0[NBLK * DH * DH];        // fc0 [l][n][k]
__device__ __half g_wcat[(NBLK - 1) * DH * DCAT]; // [i][n][ Wz_{i+1} | W1_i ]
__device__ __half g_w1l[DH * DH];              // W1 layer4 [n][k]
__device__ float  g_b0[DH];                    // lin_in_b + lin_z_b[0]
__device__ float  g_bcat[(NBLK - 1) * DH];     // b1_i + bz_{i+1}

// ---------------------------------------------------------------------------
// PTX helpers
// ---------------------------------------------------------------------------
__device__ __forceinline__ uint32_t smem_u32(const void* p) {
    uint32_t a;
    asm("{ .reg .u64 t; cvta.to.shared.u64 t, %1; cvt.u32.u64 %0, t; }" : "=r"(a) : "l"(p));
    return a;
}
__device__ __forceinline__ void ldsm_x4(uint32_t& r0, uint32_t& r1, uint32_t& r2,
                                        uint32_t& r3, uint32_t addr) {
    asm volatile("ldmatrix.sync.aligned.m8n8.x4.shared.b16 {%0,%1,%2,%3}, [%4];"
                 : "=r"(r0), "=r"(r1), "=r"(r2), "=r"(r3) : "r"(addr));
}
__device__ __forceinline__ void mma_f16(float* d, const uint32_t* a, const uint32_t* b) {
    asm volatile(
        "mma.sync.aligned.m16n8k16.row.col.f32.f16.f16.f32 "
        "{%0,%1,%2,%3}, {%4,%5,%6,%7}, {%8,%9}, {%0,%1,%2,%3};"
        : "+f"(d[0]), "+f"(d[1]), "+f"(d[2]), "+f"(d[3])
        : "r"(a[0]), "r"(a[1]), "r"(a[2]), "r"(a[3]), "r"(b[0]), "r"(b[1]));
}
__device__ __forceinline__ void cp16(uint32_t dst, const void* src) {
    asm volatile("cp.async.cg.shared.global [%0], [%1], 16;" :: "r"(dst), "l"(src));
}
#define CP_COMMIT() asm volatile("cp.async.commit_group;" ::: "memory")
#define CP_WAIT(n)  asm volatile("cp.async.wait_group %0;" :: "n"(n) : "memory")

// ---------------------------------------------------------------------------
// Prep kernels
// ---------------------------------------------------------------------------
__global__ void enc_kernel(const float* __restrict__ xyz,
                           const float* __restrict__ c2w,
                           const float* __restrict__ kmat) {
    int n = blockIdx.x * blockDim.x + threadIdx.x;
    if (n >= NPTS) return;
    int b = n / NPB;
    float p0 = xyz[n * 3 + 0], p1 = xyz[n * 3 + 1], p2 = xyz[n * 3 + 2];
    const float* M = c2w + b * 16;
    float q0 = p0 - M[3], q1 = p1 - M[7], q2 = p2 - M[11];
    float cam[3];
    #pragma unroll
    for (int i = 0; i < 3; i++)
        cam[i] = M[0 * 4 + i] * q0 + M[1 * 4 + i] * q1 + M[2 * 4 + i] * q2;
    const float* K = kmat + b * 9;
    float uw = K[0] * cam[0] + K[1] * cam[1] + K[2] * cam[2];
    float vw = K[3] * cam[0] + K[4] * cam[1] + K[5] * cam[2];
    float zw = K[6] * cam[0] + K[7] * cam[1] + K[8] * cam[2];
    float z = (fabsf(zw) < 1e-6f) ? 1e-6f : zw;
    g_uv[n * 2 + 0] = uw / z;
    g_uv[n * 2 + 1] = vw / z;
    __half* E = g_acat + (size_t)n * ACAT;     // ench at offset 0
    E[0] = __float2half_rn(cam[0]);
    E[1] = __float2half_rn(cam[1]);
    E[2] = __float2half_rn(cam[2]);
    const float TWO_PI = 6.283185307179586f;
    #pragma unroll
    for (int axis = 0; axis < 3; axis++)
        #pragma unroll
        for (int f = 0; f < NFREQ; f++) {
            float s = TWO_PI * cam[axis] * (float)(1 << f);
            E[3  + axis * NFREQ + f] = __float2half_rn(sinf(s));
            E[33 + axis * NFREQ + f] = __float2half_rn(cosf(s));
        }
    E[63] = __float2half_rn(0.0f);
}

// features [b][c][y][x] fp32 -> g_featT [b][pix][c] fp16
__global__ void transpose_feat_kernel(const float* __restrict__ feat) {
    __shared__ __half tile[32][33];
    int pxt = blockIdx.x;
    int ct  = blockIdx.y;
    int b   = blockIdx.z;
    int tid = threadIdx.x;
    int col = tid & 31;
    int rowb = tid >> 5;
    const float* fb = feat + (size_t)b * DH * NPIX;
    #pragma unroll
    for (int i = 0; i < 4; i++) {
        int c = ct * 32 + rowb + i * 8;
        tile[rowb + i * 8][col] = __float2half_rn(fb[(size_t)c * NPIX + pxt * 32 + col]);
    }
    __syncthreads();
    __half* ob = g_featT + ((size_t)b * NPIX + pxt * 32) * DH + ct * 32;
    #pragma unroll
    for (int i = 0; i < 4; i++) {
        int px = rowb + i * 8;
        ob[(size_t)px * DH + col] = tile[col][px];
    }
}

// bilinear -> al section of g_acat (stride ACAT, offset OFF_AL)
__global__ void bilinear_kernel() {
    int n = blockIdx.x * 8 + (threadIdx.x >> 5);
    int lane = threadIdx.x & 31;
    if (n >= NPTS) return;
    int b = n / NPB;
    float u = g_uv[n * 2 + 0], v = g_uv[n * 2 + 1];
    float x = fminf(fmaxf(u, 0.0f), (float)(IMGW - 1));
    float y = fminf(fmaxf(v, 0.0f), (float)(IMGH - 1));
    float x0 = floorf(x), y0 = floorf(y);
    int x0i = (int)x0, y0i = (int)y0;
    int x1i = min(x0i + 1, IMGW - 1);
    int y1i = min(y0i + 1, IMGH - 1);
    float wx = x - x0, wy = y - y0;
    float w00 = (1.0f - wx) * (1.0f - wy);
    float w01 = wx * (1.0f - wy);
    float w10 = (1.0f - wx) * wy;
    float w11 = wx * wy;
    const __half* base = g_featT + (size_t)b * NPIX * DH;
    const __half* p00 = base + (size_t)(y0i * IMGW + x0i) * DH;
    const __half* p01 = base + (size_t)(y0i * IMGW + x1i) * DH;
    const __half* p10 = base + (size_t)(y1i * IMGW + x0i) * DH;
    const __half* p11 = base + (size_t)(y1i * IMGW + x1i) * DH;
    __half* out = g_acat + (size_t)n * ACAT + OFF_AL;
    #pragma unroll
    for (int rep = 0; rep < 2; rep++) {
        int c0 = rep * 256 + lane * 8;
        uint4 a = *(const uint4*)(p00 + c0);
        uint4 bq = *(const uint4*)(p01 + c0);
        uint4 cq = *(const uint4*)(p10 + c0);
        uint4 dq = *(const uint4*)(p11 + c0);
        const __half2* ah = (const __half2*)&a;
        const __half2* bh = (const __half2*)&bq;
        const __half2* ch = (const __half2*)&cq;
        const __half2* dh = (const __half2*)&dq;
        uint4 o;
        __half2* oh = (__half2*)&o;
        #pragma unroll
        for (int i = 0; i < 4; i++) {
            float2 fa = __half22float2(ah[i]);
            float2 fbv = __half22float2(bh[i]);
            float2 fc = __half22float2(ch[i]);
            float2 fd = __half22float2(dh[i]);
            float r0 = fa.x * w00 + fbv.x * w01 + fc.x * w10 + fd.x * w11;
            float r1 = fa.y * w00 + fbv.y * w01 + fc.y * w10 + fd.y * w11;
            oh[i] = __floats2half2_rn(r0, r1);
        }
        *(uint4*)(out + c0) = o;
    }
}

// W[l][k][n] fp32 -> O [l][n][k] fp16 (all NBLK layers)
__global__ void conv_w_kernel(const float* __restrict__ W, __half* __restrict__ O,
                              int total) {
    int idx = blockIdx.x * blockDim.x + threadIdx.x;
    if (idx >= total) return;
    int l = idx >> 18;
    int rem = idx & 262143;
    int k = rem >> 9;
    int n = rem & 511;
    O[(l << 18) + n * DH + k] = __float2half_rn(W[idx]);
}

// single layer W[k][n] -> O[n][k]
__global__ void conv_w1_kernel(const float* __restrict__ W, __half* __restrict__ O) {
    int idx = blockIdx.x * blockDim.x + threadIdx.x;
    if (idx >= DH * DH) return;
    int k = idx >> 9, n = idx & 511;
    O[n * DH + k] = __float2half_rn(W[idx]);
}

// g_wcat0[n][k]: k<64 -> lin_in_w[k][n] (pad 63), else Wz0[k-64][n]
__global__ void conv_wcat0_kernel(const float* __restrict__ Win,
                                  const float* __restrict__ Wz) {
    int idx = blockIdx.x * blockDim.x + threadIdx.x;
    if (idx >= DH * DIN) return;
    int n = idx / DIN;
    int k = idx % DIN;
    float v;
    if (k < DENC) v = (k < 63) ? Win[k * DH + n] : 0.0f;
    else          v = Wz[(size_t)(k - DENC) * DH + n];
    g_wcat0[n * DIN + k] = __float2half_rn(v);
}

// concat weights: g_wcat[i][n][k<512: Wz_{i+1}[k][n] ; k>=512: W1_i[k-512][n]]
__global__ void conv_wcat_kernel(const float* __restrict__ Wz,
                                 const float* __restrict__ W1) {
    int idx = blockIdx.x * blockDim.x + threadIdx.x;
    if (idx >= (NBLK - 1) * DH * DCAT) return;
    int i = idx / (DH * DCAT);
    int rem = idx % (DH * DCAT);
    int n = rem >> 10;
    int k = rem & 1023;
    float v;
    if (k < DH) v = Wz[(size_t)(i + 1) * DH * DH + k * DH + n];
    else        v = W1[(size_t)i * DH * DH + (k - DH) * DH + n];
    g_wcat[(size_t)i * DH * DCAT + n * DCAT + k] = __float2half_rn(v);
}

// g_b0 = lin_in_b + lin_z_b[0];  g_bcat[i] = fc1_b[i] + lin_z_b[i+1]
__global__ void bias_kernel(const float* __restrict__ bin,
                            const float* __restrict__ bz,
                            const float* __restrict__ b1) {
    int idx = blockIdx.x * blockDim.x + threadIdx.x;
    if (idx < DH) g_b0[idx] = bin[idx] + bz[idx];
    idx -= DH;
    if (idx >= 0 && idx < (NBLK - 1) * DH) {
        int i = idx >> 9, n = idx & 511;
        g_bcat[idx] = b1[i * DH + n] + bz[(i + 1) * DH + n];
    }
}

// ---------------------------------------------------------------------------
// fp16 GEMM: mma.sync.m16n8k16, 3-stage cp.async, block 128x128, warp 32x64,
// K-chunk 64 (128-byte SW128 smem rows) -> half the syncs of the K32 engine.
// A: [m][lda] (Klen consumed). B: [n][Klen] packed. h stride DH, fp16 out ldo.
// Klen must be a multiple of 64 (576, 512, 1024 all are).
// ---------------------------------------------------------------------------
#define TBM 128
#define TBN 128
#define TBK 64
#define STG_A 0
#define STG_B 16384
#define STAGEB 32768
#define NSTAGE 3
#define SMEMSZ (NSTAGE * STAGEB)   // 96KB

// swizzled byte offset of 16B chunk `ch` (0..7) in 128B row `r`
#define SW128OFF(r, ch) ((uint32_t)((r) * 128 + 16 * ((ch) ^ ((r) & 7))))

template <bool ACCUM, bool WF32, bool WHALF>
__global__ void __launch_bounds__(256, 2)
gemm_tc_kernel(const __half* __restrict__ Aw, const __half* __restrict__ Bw,
               const float* __restrict__ bias, float* __restrict__ Cf,
               __half* __restrict__ Oh, int Klen, int lda, int ldo) {
    extern __shared__ char smem[];
    const uint32_t sbase = smem_u32(smem);
    const int tid = threadIdx.x;
    const int lane = tid & 31;
    const int wid = tid >> 5;
    const int wm = wid & 3;
    const int wn = wid >> 2;
    const int m0 = blockIdx.y * TBM;
    const int n0 = blockIdx.x * TBN;
    const int NCH = Klen >> 6;

    const __half* pA = Aw + (size_t)m0 * lda;
    const __half* pB = Bw + (size_t)n0 * Klen;

    float acc[2][8][4];
    #pragma unroll
    for (int t = 0; t < 2; t++)
        #pragma unroll
        for (int j = 0; j < 8; j++)
            #pragma unroll
            for (int q = 0; q < 4; q++) acc[t][j][q] = 0.0f;

    // loader: A 1024 + B 1024 lines of 16B, 8 per thread
    auto load_stage = [&](int c) {
        const uint32_t bb = sbase + (c % NSTAGE) * STAGEB;
        const int k0 = c * TBK;
        #pragma unroll
        for (int i = 0; i < 4; i++) {
            int idx = tid + i * 256;
            int r = idx >> 3, ch = idx & 7;
            uint32_t so = SW128OFF(r, ch);
            cp16(bb + STG_A + so, pA + (size_t)r * lda + k0 + ch * 8);
            cp16(bb + STG_B + so, pB + (size_t)r * Klen + k0 + ch * 8);
        }
    };

    load_stage(0);
    CP_COMMIT();
    if (1 < NCH) load_stage(1);
    CP_COMMIT();

    for (int c = 0; c < NCH; c++) {
        CP_WAIT(1);
        __syncthreads();
        if (c + 2 < NCH) load_stage(c + 2);
        CP_COMMIT();

        const uint32_t bb = sbase + (c % NSTAGE) * STAGEB;
        #pragma unroll
        for (int s = 0; s < 4; s++) {            // four k16 steps per chunk
            uint32_t ah[2][4], bh[8][2];
            #pragma unroll
            for (int t = 0; t < 2; t++) {
                int r = wm * 32 + t * 16 + (lane & 15);
                int ch = 2 * s + (lane >> 4);
                ldsm_x4(ah[t][0], ah[t][1], ah[t][2], ah[t][3], bb + STG_A + SW128OFF(r, ch));
            }
            #pragma unroll
            for (int p = 0; p < 4; p++) {
                int nr = wn * 64 + p * 16 + (lane & 7) + ((lane >> 4) << 3);
                int ch = 2 * s + ((lane >> 3) & 1);
                ldsm_x4(bh[2 * p][0], bh[2 * p][1], bh[2 * p + 1][0], bh[2 * p + 1][1],
                        bb + STG_B + SW128OFF(nr, ch));
            }
            #pragma unroll
            for (int t = 0; t < 2; t++)
                #pragma unroll
                for (int j = 0; j < 8; j++)
                    mma_f16(acc[t][j], ah[t], bh[j]);
        }
    }

    // ---- epilogue ----
    #pragma unroll
    for (int t = 0; t < 2; t++) {
        #pragma unroll
        for (int half = 0; half < 2; half++) {
            int m = m0 + wm * 32 + t * 16 + half * 8 + (lane >> 2);
            float* crow = (WF32 || ACCUM) ? (Cf + (size_t)m * DH) : nullptr;
            #pragma unroll
            for (int j = 0; j < 8; j++) {
                int col = n0 + wn * 64 + j * 8 + (lane & 3) * 2;
                float v0 = acc[t][j][half * 2 + 0] + bias[col];
                float v1 = acc[t][j][half * 2 + 1] + bias[col + 1];
                if (ACCUM) {
                    float2 o = *(const float2*)(crow + col);
                    v0 += o.x; v1 += o.y;
                }
                if (WF32) *(float2*)(crow + col) = make_float2(v0, v1);
                if (WHALF) {
                    __half h0 = __float2half_rn(fmaxf(v0, 0.0f));
                    __half h1 = __float2half_rn(fmaxf(v1, 0.0f));
                    *(__half2*)(Oh + (size_t)m * ldo + col) = __half2{h0, h1};
                }
            }
        }
    }
}

// ---------------------------------------------------------------------------
// sigma = exp(relu(h) @ w_out + b_out), one warp per point
// ---------------------------------------------------------------------------
__global__ void sigma_kernel(const float* __restrict__ w_out,
                             const float* __restrict__ b_out,
                             float* __restrict__ out) {
    int gtid = blockIdx.x * blockDim.x + threadIdx.x;
    int n = gtid >> 5, lane = gtid & 31;
    if (n >= NPTS) return;
    const float* hrow = g_h + (size_t)n * DH;
    float s = 0.0f;
    #pragma unroll
    for (int k = lane; k < DH; k += 32)
        s = fmaf(fmaxf(hrow[k], 0.0f), w_out[k], s);
    #pragma unroll
    for (int off = 16; off > 0; off >>= 1)
        s += __shfl_down_sync(0xFFFFFFFF, s, off);
    if (lane == 0) out[n] = expf(s + b_out[0]);
}

// ---------------------------------------------------------------------------
// Launch
// ---------------------------------------------------------------------------
template <typename T>
static T* sym(const T& s) {
    void* p = nullptr;
    cudaGetSymbolAddress(&p, s);
    return (T*)p;
}

extern "C" void kernel_launch(void* const* d_in, const int* in_sizes, int n_in,
                              void* d_out, int out_size) {
    const float* world_xyz = (const float*)d_in[0];
    const float* c2w       = (const float*)d_in[1];
    const float* k_mat     = (const float*)d_in[2];
    const float* features  = (const float*)d_in[3];
    const float* lin_in_w  = (const float*)d_in[4];
    const float* lin_in_b  = (const float*)d_in[5];
    const float* lin_z_w   = (const float*)d_in[6];
    const float* lin_z_b   = (const float*)d_in[7];
    const float* fc0_w     = (const float*)d_in[8];
    const float* fc0_b     = (const float*)d_in[9];
    const float* fc1_w     = (const float*)d_in[10];
    const float* fc1_b     = (const float*)d_in[11];
    const float* lin_out_w = (const float*)d_in[12];
    const float* lin_out_b = (const float*)d_in[13];
    float* out = (float*)d_out;

    cudaFuncSetAttribute(gemm_tc_kernel<false, true,  true >, cudaFuncAttributeMaxDynamicSharedMemorySize, SMEMSZ);
    cudaFuncSetAttribute(gemm_tc_kernel<true,  true,  true >, cudaFuncAttributeMaxDynamicSharedMemorySize, SMEMSZ);
    cudaFuncSetAttribute(gemm_tc_kernel<false, false, true >, cudaFuncAttributeMaxDynamicSharedMemorySize, SMEMSZ);
    cudaFuncSetAttribute(gemm_tc_kernel<true,  true,  false>, cudaFuncAttributeMaxDynamicSharedMemorySize, SMEMSZ);

    float*  p_h     = (float*)sym(g_h);
    __half* p_acat  = (__half*)sym(g_acat);
    __half* p_t     = (__half*)sym(g_t);
    __half* p_wcat0 = (__half*)sym(g_wcat0);
    __half* p_w0    = (__half*)sym(g_w0);
    __half* p_wcat  = (__half*)sym(g_wcat);
    __half* p_w1l   = (__half*)sym(g_w1l);
    float*  p_b0    = (float*)sym(g_b0);
    float*  p_bcat  = (float*)sym(g_bcat);

    enc_kernel<<<(NPTS + 255) / 256, 256>>>(world_xyz, c2w, k_mat);
    transpose_feat_kernel<<<dim3(NPIX / 32, DH / 32, 2), 256>>>(features);
    bilinear_kernel<<<NPTS / 8, 256>>>();

    conv_w_kernel<<<(NBLK * DH * DH + 255) / 256, 256>>>(fc0_w, p_w0, NBLK * DH * DH);
    conv_w1_kernel<<<(DH * DH + 255) / 256, 256>>>(fc1_w + (size_t)(NBLK - 1) * DH * DH, p_w1l);
    conv_wcat0_kernel<<<(DH * DIN + 255) / 256, 256>>>(lin_in_w, lin_z_w);
    conv_wcat_kernel<<<((NBLK - 1) * DH * DCAT + 255) / 256, 256>>>(lin_z_w, fc1_w);
    bias_kernel<<<(NBLK * DH + 255) / 256, 256>>>(lin_in_b, lin_z_b, fc1_b);

    dim3 grid(DH / TBN, NPTS / TBM);   // (4, 768)

    // h = [ench|al] @ [Win|Wz0] + (b_in + bz0) ; t = relu(h)
    gemm_tc_kernel<false, true, true><<<grid, 256, SMEMSZ>>>(
        p_acat, p_wcat0, p_b0, p_h, p_t, DIN, ACAT, DH);

    for (int i = 0; i < NBLK; i++) {
        // u = relu(t @ W0_i + b0_i)  -> g_acat u section
        gemm_tc_kernel<false, false, true><<<grid, 256, SMEMSZ>>>(
            p_t, p_w0 + (size_t)i * DH * DH, fc0_b + (size_t)i * DH,
            nullptr, p_acat + OFF_U, DH, DH, ACAT);
        if (i < NBLK - 1) {
            // h += [al|u] @ [Wz_{i+1}|W1_i] + (b1_i + bz_{i+1}) ; t = relu(h)
            gemm_tc_kernel<true, true, true><<<grid, 256, SMEMSZ>>>(
                p_acat + OFF_AL, p_wcat + (size_t)i * DH * DCAT, p_bcat + (size_t)i * DH,
                p_h, p_t, DCAT, ACAT, DH);
        } else {
            // h += u @ W1_4 + b1_4
            gemm_tc_kernel<true, true, false><<<grid, 256, SMEMSZ>>>(
                p_acat + OFF_U, p_w1l, fc1_b + (size_t)(NBLK - 1) * DH,
                p_h, nullptr, DH, ACAT, 0);
        }
    }

    sigma_kernel<<<(NPTS * 32 + 255) / 256, 256>>>(lin_out_w, lin_out_b, out);
}

// round 15
// speedup vs baseline: 1.3483x; 1.0415x over previous
#include <cuda_runtime.h>
#include <cuda_fp16.h>
#include <cstdint>
#include <math.h>

// ---------------------------------------------------------------------------
// Problem constants
// ---------------------------------------------------------------------------
#define NPTS      98304
#define NPB       49152
#define DH        512
#define NBLK      5
#define NFREQ     10
#define IMGH      128
#define IMGW      128
#define DENC      64
#define NPIX      (IMGH * IMGW)
#define DCAT      1024                  // [al | u] concat K
#define DIN       (DENC + DH)           // [ench | al] concat K = 576
#define ACAT      (DENC + DH + DH)      // activation row stride = 1088
#define OFF_AL    DENC                  // 64
#define OFF_U     (DENC + DH)           // 576

// ---------------------------------------------------------------------------
// Scratch
// ---------------------------------------------------------------------------
__device__ float  g_uv[NPTS * 2];
__device__ float  g_h[NPTS * DH];              // fp32 residual stream
__device__ __half g_featT[2 * NPIX * DH];      // transposed features [b][pix][c]
__device__ __half g_acat[NPTS * ACAT];         // [ench | al | u]
__device__ __half g_t[NPTS * DH];              // relu(h)
__device__ __half g_wcat0[DH * DIN];           // [n][ Win | Wz0 ]
__device__ __half g_w0[NBLK * DH * DH];        // fc0 [l][n][k]
__device__ __half g_wcat[(NBLK - 1) * DH * DCAT]; // [i][n][ Wz_{i+1} | W1_i ]
__device__ __half g_w1l[DH * DH];              // W1 layer4 [n][k]
__device__ float  g_b0[DH];                    // lin_in_b + lin_z_b[0]
__device__ float  g_bcat[(NBLK - 1) * DH];     // b1_i + bz_{i+1}
__device__ float  g_part[8 * NPTS];            // sigma partials (deterministic)

// ---------------------------------------------------------------------------
// PTX helpers
// ---------------------------------------------------------------------------
__device__ __forceinline__ uint32_t smem_u32(const void* p) {
    uint32_t a;
    asm("{ .reg .u64 t; cvta.to.shared.u64 t, %1; cvt.u32.u64 %0, t; }" : "=r"(a) : "l"(p));
    return a;
}
__device__ __forceinline__ void ldsm_x4(uint32_t& r0, uint32_t& r1, uint32_t& r2,
                                        uint32_t& r3, uint32_t addr) {
    asm volatile("ldmatrix.sync.aligned.m8n8.x4.shared.b16 {%0,%1,%2,%3}, [%4];"
                 : "=r"(r0), "=r"(r1), "=r"(r2), "=r"(r3) : "r"(addr));
}
__device__ __forceinline__ void mma_f16(float* d, const uint32_t* a, const uint32_t* b) {
    asm volatile(
        "mma.sync.aligned.m16n8k16.row.col.f32.f16.f16.f32 "
        "{%0,%1,%2,%3}, {%4,%5,%6,%7}, {%8,%9}, {%0,%1,%2,%3};"
        : "+f"(d[0]), "+f"(d[1]), "+f"(d[2]), "+f"(d[3])
        : "r"(a[0]), "r"(a[1]), "r"(a[2]), "r"(a[3]), "r"(b[0]), "r"(b[1]));
}
__device__ __forceinline__ void cp16(uint32_t dst, const void* src) {
    asm volatile("cp.async.cg.shared.global [%0], [%1], 16;" :: "r"(dst), "l"(src));
}
#define CP_COMMIT() asm volatile("cp.async.commit_group;" ::: "memory")
#define CP_WAIT(n)  asm volatile("cp.async.wait_group %0;" :: "n"(n) : "memory")

// ---------------------------------------------------------------------------
// Prep kernels
// ---------------------------------------------------------------------------
__global__ void enc_kernel(const float* __restrict__ xyz,
                           const float* __restrict__ c2w,
                           const float* __restrict__ kmat) {
    int n = blockIdx.x * blockDim.x + threadIdx.x;
    if (n >= NPTS) return;
    int b = n / NPB;
    float p0 = xyz[n * 3 + 0], p1 = xyz[n * 3 + 1], p2 = xyz[n * 3 + 2];
    const float* M = c2w + b * 16;
    float q0 = p0 - M[3], q1 = p1 - M[7], q2 = p2 - M[11];
    float cam[3];
    #pragma unroll
    for (int i = 0; i < 3; i++)
        cam[i] = M[0 * 4 + i] * q0 + M[1 * 4 + i] * q1 + M[2 * 4 + i] * q2;
    const float* K = kmat + b * 9;
    float uw = K[0] * cam[0] + K[1] * cam[1] + K[2] * cam[2];
    float vw = K[3] * cam[0] + K[4] * cam[1] + K[5] * cam[2];
    float zw = K[6] * cam[0] + K[7] * cam[1] + K[8] * cam[2];
    float z = (fabsf(zw) < 1e-6f) ? 1e-6f : zw;
    g_uv[n * 2 + 0] = uw / z;
    g_uv[n * 2 + 1] = vw / z;

    __align__(16) __half e[64];
    e[0] = __float2half_rn(cam[0]);
    e[1] = __float2half_rn(cam[1]);
    e[2] = __float2half_rn(cam[2]);
    const float TWO_PI = 6.283185307179586f;
    #pragma unroll
    for (int axis = 0; axis < 3; axis++)
        #pragma unroll
        for (int f = 0; f < NFREQ; f++) {
            float s = TWO_PI * cam[axis] * (float)(1 << f);
            e[3  + axis * NFREQ + f] = __float2half_rn(sinf(s));
            e[33 + axis * NFREQ + f] = __float2half_rn(cosf(s));
        }
    e[63] = __float2half_rn(0.0f);
    uint4* dst = (uint4*)(g_acat + (size_t)n * ACAT);
    const uint4* src = (const uint4*)e;
    #pragma unroll
    for (int i = 0; i < 8; i++) dst[i] = src[i];
}

// features [b][c][y][x] fp32 -> g_featT [b][pix][c] fp16
__global__ void transpose_feat_kernel(const float* __restrict__ feat) {
    __shared__ __half tile[32][33];
    int pxt = blockIdx.x;
    int ct  = blockIdx.y;
    int b   = blockIdx.z;
    int tid = threadIdx.x;
    int col = tid & 31;
    int rowb = tid >> 5;
    const float* fb = feat + (size_t)b * DH * NPIX;
    #pragma unroll
    for (int i = 0; i < 4; i++) {
        int c = ct * 32 + rowb + i * 8;
        tile[rowb + i * 8][col] = __float2half_rn(fb[(size_t)c * NPIX + pxt * 32 + col]);
    }
    __syncthreads();
    __half* ob = g_featT + ((size_t)b * NPIX + pxt * 32) * DH + ct * 32;
    #pragma unroll
    for (int i = 0; i < 4; i++) {
        int px = rowb + i * 8;
        ob[(size_t)px * DH + col] = tile[col][px];
    }
}

// bilinear -> al section of g_acat (stride ACAT, offset OFF_AL)
__global__ void bilinear_kernel() {
    int n = blockIdx.x * 8 + (threadIdx.x >> 5);
    int lane = threadIdx.x & 31;
    if (n >= NPTS) return;
    int b = n / NPB;
    float u = g_uv[n * 2 + 0], v = g_uv[n * 2 + 1];
    float x = fminf(fmaxf(u, 0.0f), (float)(IMGW - 1));
    float y = fminf(fmaxf(v, 0.0f), (float)(IMGH - 1));
    float x0 = floorf(x), y0 = floorf(y);
    int x0i = (int)x0, y0i = (int)y0;
    int x1i = min(x0i + 1, IMGW - 1);
    int y1i = min(y0i + 1, IMGH - 1);
    float wx = x - x0, wy = y - y0;
    float w00 = (1.0f - wx) * (1.0f - wy);
    float w01 = wx * (1.0f - wy);
    float w10 = (1.0f - wx) * wy;
    float w11 = wx * wy;
    const __half* base = g_featT + (size_t)b * NPIX * DH;
    const __half* p00 = base + (size_t)(y0i * IMGW + x0i) * DH;
    const __half* p01 = base + (size_t)(y0i * IMGW + x1i) * DH;
    const __half* p10 = base + (size_t)(y1i * IMGW + x0i) * DH;
    const __half* p11 = base + (size_t)(y1i * IMGW + x1i) * DH;
    __half* out = g_acat + (size_t)n * ACAT + OFF_AL;
    #pragma unroll
    for (int rep = 0; rep < 2; rep++) {
        int c0 = rep * 256 + lane * 8;
        uint4 a = *(const uint4*)(p00 + c0);
        uint4 bq = *(const uint4*)(p01 + c0);
        uint4 cq = *(const uint4*)(p10 + c0);
        uint4 dq = *(const uint4*)(p11 + c0);
        const __half2* ah = (const __half2*)&a;
        const __half2* bh = (const __half2*)&bq;
        const __half2* ch = (const __half2*)&cq;
        const __half2* dh = (const __half2*)&dq;
        uint4 o;
        __half2* oh = (__half2*)&o;
        #pragma unroll
        for (int i = 0; i < 4; i++) {
            float2 fa = __half22float2(ah[i]);
            float2 fbv = __half22float2(bh[i]);
            float2 fc = __half22float2(ch[i]);
            float2 fd = __half22float2(dh[i]);
            float r0 = fa.x * w00 + fbv.x * w01 + fc.x * w10 + fd.x * w11;
            float r1 = fa.y * w00 + fbv.y * w01 + fc.y * w10 + fd.y * w11;
            oh[i] = __floats2half2_rn(r0, r1);
        }
        *(uint4*)(out + c0) = o;
    }
}

// W[l][k][n] fp32 -> O [l][n][k] fp16 (all NBLK layers)
__global__ void conv_w_kernel(const float* __restrict__ W, __half* __restrict__ O,
                              int total) {
    int idx = blockIdx.x * blockDim.x + threadIdx.x;
    if (idx >= total) return;
    int l = idx >> 18;
    int rem = idx & 262143;
    int k = rem >> 9;
    int n = rem & 511;
    O[(l << 18) + n * DH + k] = __float2half_rn(W[idx]);
}

// single layer W[k][n] -> O[n][k]
__global__ void conv_w1_kernel(const float* __restrict__ W, __half* __restrict__ O) {
    int idx = blockIdx.x * blockDim.x + threadIdx.x;
    if (idx >= DH * DH) return;
    int k = idx >> 9, n = idx & 511;
    O[n * DH + k] = __float2half_rn(W[idx]);
}

// g_wcat0[n][k]: k<64 -> lin_in_w[k][n] (pad 63), else Wz0[k-64][n]
__global__ void conv_wcat0_kernel(const float* __restrict__ Win,
                                  const float* __restrict__ Wz) {
    int idx = blockIdx.x * blockDim.x + threadIdx.x;
    if (idx >= DH * DIN) return;
    int n = idx / DIN;
    int k = idx % DIN;
    float v;
    if (k < DENC) v = (k < 63) ? Win[k * DH + n] : 0.0f;
    else          v = Wz[(size_t)(k - DENC) * DH + n];
    g_wcat0[n * DIN + k] = __float2half_rn(v);
}

// concat weights: g_wcat[i][n][k<512: Wz_{i+1}[k][n] ; k>=512: W1_i[k-512][n]]
__global__ void conv_wcat_kernel(const float* __restrict__ Wz,
                                 const float* __restrict__ W1) {
    int idx = blockIdx.x * blockDim.x + threadIdx.x;
    if (idx >= (NBLK - 1) * DH * DCAT) return;
    int i = idx / (DH * DCAT);
    int rem = idx % (DH * DCAT);
    int n = rem >> 10;
    int k = rem & 1023;
    float v;
    if (k < DH) v = Wz[(size_t)(i + 1) * DH * DH + k * DH + n];
    else        v = W1[(size_t)i * DH * DH + (k - DH) * DH + n];
    g_wcat[(size_t)i * DH * DCAT + n * DCAT + k] = __float2half_rn(v);
}

// g_b0 = lin_in_b + lin_z_b[0];  g_bcat[i] = fc1_b[i] + lin_z_b[i+1]
__global__ void bias_kernel(const float* __restrict__ bin,
                            const float* __restrict__ bz,
                            const float* __restrict__ b1) {
    int idx = blockIdx.x * blockDim.x + threadIdx.x;
    if (idx < DH) g_b0[idx] = bin[idx] + bz[idx];
    idx -= DH;
    if (idx >= 0 && idx < (NBLK - 1) * DH) {
        int i = idx >> 9, n = idx & 511;
        g_bcat[idx] = b1[i * DH + n] + bz[(i + 1) * DH + n];
    }
}

// ---------------------------------------------------------------------------
// fp16 GEMM: mma.sync.m16n8k16, 3-stage cp.async, block 128x128, warp 32x64,
// K-chunk 64 (128B SW128 rows).  Optional fused sigma partials (WSIG).
// ---------------------------------------------------------------------------
#define TBM 128
#define TBN 128
#define TBK 64
#define STG_A 0
#define STG_B 16384
#define STAGEB 32768
#define NSTAGE 3
#define SMEMSZ (NSTAGE * STAGEB)   // 96KB

#define SW128OFF(r, ch) ((uint32_t)((r) * 128 + 16 * ((ch) ^ ((r) & 7))))

template <bool ACCUM, bool WF32, bool WHALF, bool WSIG>
__global__ void __launch_bounds__(256, 2)
gemm_tc_kernel(const __half* __restrict__ Aw, const __half* __restrict__ Bw,
               const float* __restrict__ bias, float* __restrict__ Cf,
               __half* __restrict__ Oh, const float* __restrict__ wout,
               float* __restrict__ part, int Klen, int lda, int ldo) {
    extern __shared__ char smem[];
    const uint32_t sbase = smem_u32(smem);
    const int tid = threadIdx.x;
    const int lane = tid & 31;
    const int wid = tid >> 5;
    const int wm = wid & 3;
    const int wn = wid >> 2;
    const int m0 = blockIdx.y * TBM;
    const int n0 = blockIdx.x * TBN;
    const int NCH = Klen >> 6;

    const __half* pA = Aw + (size_t)m0 * lda;
    const __half* pB = Bw + (size_t)n0 * Klen;

    float acc[2][8][4];
    #pragma unroll
    for (int t = 0; t < 2; t++)
        #pragma unroll
        for (int j = 0; j < 8; j++)
            #pragma unroll
            for (int q = 0; q < 4; q++) acc[t][j][q] = 0.0f;

    auto load_stage = [&](int c) {
        const uint32_t bb = sbase + (c % NSTAGE) * STAGEB;
        const int k0 = c * TBK;
        #pragma unroll
        for (int i = 0; i < 4; i++) {
            int idx = tid + i * 256;
            int r = idx >> 3, ch = idx & 7;
            uint32_t so = SW128OFF(r, ch);
            cp16(bb + STG_A + so, pA + (size_t)r * lda + k0 + ch * 8);
            cp16(bb + STG_B + so, pB + (size_t)r * Klen + k0 + ch * 8);
        }
    };

    load_stage(0);
    CP_COMMIT();
    if (1 < NCH) load_stage(1);
    CP_COMMIT();

    for (int c = 0; c < NCH; c++) {
        CP_WAIT(1);
        __syncthreads();
        if (c + 2 < NCH) load_stage(c + 2);
        CP_COMMIT();

        const uint32_t bb = sbase + (c % NSTAGE) * STAGEB;
        #pragma unroll
        for (int s = 0; s < 4; s++) {
            uint32_t ah[2][4], bh[8][2];
            #pragma unroll
            for (int t = 0; t < 2; t++) {
                int r = wm * 32 + t * 16 + (lane & 15);
                int ch = 2 * s + (lane >> 4);
                ldsm_x4(ah[t][0], ah[t][1], ah[t][2], ah[t][3], bb + STG_A + SW128OFF(r, ch));
            }
            #pragma unroll
            for (int p = 0; p < 4; p++) {
                int nr = wn * 64 + p * 16 + (lane & 7) + ((lane >> 4) << 3);
                int ch = 2 * s + ((lane >> 3) & 1);
                ldsm_x4(bh[2 * p][0], bh[2 * p][1], bh[2 * p + 1][0], bh[2 * p + 1][1],
                        bb + STG_B + SW128OFF(nr, ch));
            }
            #pragma unroll
            for (int t = 0; t < 2; t++)
                #pragma unroll
                for (int j = 0; j < 8; j++)
                    mma_f16(acc[t][j], ah[t], bh[j]);
        }
    }

    // ---- epilogue ----
    #pragma unroll
    for (int t = 0; t < 2; t++) {
        #pragma unroll
        for (int half = 0; half < 2; half++) {
            int m = m0 + wm * 32 + t * 16 + half * 8 + (lane >> 2);
            float* crow = (WF32 || ACCUM) ? (Cf + (size_t)m * DH) : nullptr;
            float sig = 0.0f;
            #pragma unroll
            for (int j = 0; j < 8; j++) {
                int col = n0 + wn * 64 + j * 8 + (lane & 3) * 2;
                float v0 = acc[t][j][half * 2 + 0] + bias[col];
                float v1 = acc[t][j][half * 2 + 1] + bias[col + 1];
                if (ACCUM) {
                    float2 o = *(const float2*)(crow + col);
                    v0 += o.x; v1 += o.y;
                }
                if (WF32) *(float2*)(crow + col) = make_float2(v0, v1);
                if (WHALF) {
                    __half h0 = __float2half_rn(fmaxf(v0, 0.0f));
                    __half h1 = __float2half_rn(fmaxf(v1, 0.0f));
                    *(__half2*)(Oh + (size_t)m * ldo + col) = __half2{h0, h1};
                }
                if (WSIG) {
                    sig = fmaf(fmaxf(v0, 0.0f), wout[col], sig);
                    sig = fmaf(fmaxf(v1, 0.0f), wout[col + 1], sig);
                }
            }
            if (WSIG) {
                sig += __shfl_xor_sync(0xFFFFFFFF, sig, 1);
                sig += __shfl_xor_sync(0xFFFFFFFF, sig, 2);
                if ((lane & 3) == 0)
                    part[(size_t)(blockIdx.x * 2 + wn) * NPTS + m] = sig;
            }
        }
    }
}

// out[n] = exp(sum of 8 partials + b_out)
__global__ void sigexp_kernel(const float* __restrict__ b_out,
                              float* __restrict__ out) {
    int n = blockIdx.x * blockDim.x + threadIdx.x;
    if (n >= NPTS) return;
    float s = b_out[0];
    #pragma unroll
    for (int p = 0; p < 8; p++) s += g_part[(size_t)p * NPTS + n];
    out[n] = expf(s);
}

// ---------------------------------------------------------------------------
// Launch
// ---------------------------------------------------------------------------
template <typename T>
static T* sym(const T& s) {
    void* p = nullptr;
    cudaGetSymbolAddress(&p, s);
    return (T*)p;
}

extern "C" void kernel_launch(void* const* d_in, const int* in_sizes, int n_in,
                              void* d_out, int out_size) {
    const float* world_xyz = (const float*)d_in[0];
    const float* c2w       = (const float*)d_in[1];
    const float* k_mat     = (const float*)d_in[2];
    const float* features  = (const float*)d_in[3];
    const float* lin_in_w  = (const float*)d_in[4];
    const float* lin_in_b  = (const float*)d_in[5];
    const float* lin_z_w   = (const float*)d_in[6];
    const float* lin_z_b   = (const float*)d_in[7];
    const float* fc0_w     = (const float*)d_in[8];
    const float* fc0_b     = (const float*)d_in[9];
    const float* fc1_w     = (const float*)d_in[10];
    const float* fc1_b     = (const float*)d_in[11];
    const float* lin_out_w = (const float*)d_in[12];
    const float* lin_out_b = (const float*)d_in[13];
    float* out = (float*)d_out;

    cudaFuncSetAttribute(gemm_tc_kernel<false, true,  true,  false>, cudaFuncAttributeMaxDynamicSharedMemorySize, SMEMSZ);
    cudaFuncSetAttribute(gemm_tc_kernel<true,  true,  true,  false>, cudaFuncAttributeMaxDynamicSharedMemorySize, SMEMSZ);
    cudaFuncSetAttribute(gemm_tc_kernel<false, false, true,  false>, cudaFuncAttributeMaxDynamicSharedMemorySize, SMEMSZ);
    cudaFuncSetAttribute(gemm_tc_kernel<true,  false, false, true >, cudaFuncAttributeMaxDynamicSharedMemorySize, SMEMSZ);

    float*  p_h     = (float*)sym(g_h);
    __half* p_acat  = (__half*)sym(g_acat);
    __half* p_t     = (__half*)sym(g_t);
    __half* p_wcat0 = (__half*)sym(g_wcat0);
    __half* p_w0    = (__half*)sym(g_w0);
    __half* p_wcat  = (__half*)sym(g_wcat);
    __half* p_w1l   = (__half*)sym(g_w1l);
    float*  p_b0    = (float*)sym(g_b0);
    float*  p_bcat  = (float*)sym(g_bcat);
    float*  p_part  = (float*)sym(g_part);

    enc_kernel<<<(NPTS + 255) / 256, 256>>>(world_xyz, c2w, k_mat);
    transpose_feat_kernel<<<dim3(NPIX / 32, DH / 32, 2), 256>>>(features);
    bilinear_kernel<<<NPTS / 8, 256>>>();

    conv_w_kernel<<<(NBLK * DH * DH + 255) / 256, 256>>>(fc0_w, p_w0, NBLK * DH * DH);
    conv_w1_kernel<<<(DH * DH + 255) / 256, 256>>>(fc1_w + (size_t)(NBLK - 1) * DH * DH, p_w1l);
    conv_wcat0_kernel<<<(DH * DIN + 255) / 256, 256>>>(lin_in_w, lin_z_w);
    conv_wcat_kernel<<<((NBLK - 1) * DH * DCAT + 255) / 256, 256>>>(lin_z_w, fc1_w);
    bias_kernel<<<(NBLK * DH + 255) / 256, 256>>>(lin_in_b, lin_z_b, fc1_b);

    dim3 grid(DH / TBN, NPTS / TBM);   // (4, 768)

    // h = [ench|al] @ [Win|Wz0] + (b_in + bz0) ; t = relu(h)
    gemm_tc_kernel<false, true, true, false><<<grid, 256, SMEMSZ>>>(
        p_acat, p_wcat0, p_b0, p_h, p_t, nullptr, nullptr, DIN, ACAT, DH);

    for (int i = 0; i < NBLK; i++) {
        // u = relu(t @ W0_i + b0_i)  -> g_acat u section
        gemm_tc_kernel<false, false, true, false><<<grid, 256, SMEMSZ>>>(
            p_t, p_w0 + (size_t)i * DH * DH, fc0_b + (size_t)i * DH,
            nullptr, p_acat + OFF_U, nullptr, nullptr, DH, DH, ACAT);
        if (i < NBLK - 1) {
            // h += [al|u] @ [Wz_{i+1}|W1_i] + (b1_i + bz_{i+1}) ; t = relu(h)
            gemm_tc_kernel<true, true, true, false><<<grid, 256, SMEMSZ>>>(
                p_acat + OFF_AL, p_wcat + (size_t)i * DH * DCAT, p_bcat + (size_t)i * DH,
                p_h, p_t, nullptr, nullptr, DCAT, ACAT, DH);
        } else {
            // final: h_last = h + u @ W1_4 + b1_4 ; sigma partials fused
            gemm_tc_kernel<true, false, false, true><<<grid, 256, SMEMSZ>>>(
                p_acat + OFF_U, p_w1l, fc1_b + (size_t)(NBLK - 1) * DH,
                p_h, nullptr, lin_out_w, p_part, DH, ACAT, 0);
        }
    }

    sigexp_kernel<<<(NPTS + 255) / 256, 256>>>(lin_out_b, out);
}